// round 2
// baseline (speedup 1.0000x reference)
#include <cuda_runtime.h>
#include <math.h>

// ---------------------------------------------------------------------------
// MinkUNet block, round 2: BN stats fused into producer kernels (per-block
// warp-shuffle partials, deterministic), parallel finalize.
// ---------------------------------------------------------------------------

#define MAXN 131072
#define MAXM 131072
#define MAXB 64
#define MAXBLK 520

__device__ __align__(16) float dH0 [MAXN*32];   // conv0 raw
__device__ __align__(16) float dR1 [MAXN*16];   // h@Wb1 raw
__device__ __align__(16) float dR2 [MAXN*16];   // conv3 raw
__device__ __align__(16) float dY3 [MAXN*64];   // r@Wb3 raw
__device__ __align__(16) float dYDS[MAXN*64];   // h@Wds raw
__device__ __align__(16) float dH2 [MAXN*64];   // residual out
__device__ __align__(16) float dORAW[MAXM*64];  // conv2 raw
__device__ __align__(16) float dT  [MAXB*32];   // time mlp out
__device__ float dPA[MAXBLK*128];               // partials [block][2C] (sum,sumsq)
__device__ float dPB[MAXBLK*128];               // second partials (blockin YDS)
__device__ float dSC[6][64];                    // per-BN scale
__device__ float dSH[6][64];                    // per-BN shift

// ---------------------------------------------------------------------------
// Per-block stats epilogue: acc[C] per thread (zero for invalid rows).
// Warp shfl reduce (fixed order) -> smem -> cross-warp ordered sum -> partOut.
// sred must hold NW*2*C floats. Deterministic.
template<int C>
__device__ __forceinline__ void block_stats(const float* acc, float* sred,
                                            float* partOut) {
    const int NW = 8;                              // 256-thread blocks
    int lane = threadIdx.x & 31, wid = threadIdx.x >> 5;
    #pragma unroll
    for (int c = 0; c < C; c++) {
        float s = acc[c];
        float q = s * s;
        #pragma unroll
        for (int o = 16; o; o >>= 1) {
            s += __shfl_down_sync(0xffffffffu, s, o);
            q += __shfl_down_sync(0xffffffffu, q, o);
        }
        if (lane == 0) { sred[wid*2*C + 2*c] = s; sred[wid*2*C + 2*c + 1] = q; }
    }
    __syncthreads();
    if (threadIdx.x < 2*C) {
        float t = 0.f;
        #pragma unroll
        for (int w = 0; w < NW; w++) t += sred[w*2*C + threadIdx.x];
        partOut[threadIdx.x] = t;
    }
    __syncthreads();
}

// ---------------------------------------------------------------------------
// Parallel deterministic finalize: reduce nblocks partials -> scale/shift.
__device__ __forceinline__ void fin_body(const float* part, int nblocks, int C,
                                         int rows, const float* g, const float* b,
                                         int slot, float* red) {
    int t = threadIdx.x;
    int C2 = 2*C;
    if (t < C2*8) {
        int sub = t / C2, e = t - sub*C2;
        float s = 0.f;
        for (int i = sub; i < nblocks; i += 8) s += part[i*C2 + e];
        red[sub*C2 + e] = s;
    }
    __syncthreads();
    if (t < C) {
        float S = 0.f, SS = 0.f;
        #pragma unroll
        for (int k = 0; k < 8; k++) { S += red[k*C2 + 2*t]; SS += red[k*C2 + 2*t + 1]; }
        float inv  = 1.f / (float)rows;
        float mean = S * inv;
        float var  = SS * inv - mean*mean;
        float sc   = g[t] * rsqrtf(var + 1e-5f);
        dSC[slot][t] = sc;
        dSH[slot][t] = b[t] - mean*sc;
    }
}

__global__ void k_fin(const float* __restrict__ part, int nblocks, int C, int rows,
                      const float* __restrict__ g, const float* __restrict__ b,
                      int slot) {
    __shared__ float red[8*128];
    fin_body(part, nblocks, C, rows, g, b, slot, red);
}

// two finalizes in one launch (R1 slot1 C16 from dPA, YDS slot4 C64 from dPB)
__global__ void k_fin2(int nblocks, int rows,
                       const float* __restrict__ g1, const float* __restrict__ b1,
                       const float* __restrict__ g4, const float* __restrict__ b4) {
    __shared__ float red[8*128];
    if (blockIdx.x == 0) fin_body(dPA, nblocks, 16, rows, g1, b1, 1, red);
    else                 fin_body(dPB, nblocks, 64, rows, g4, b4, 4, red);
}

// ---------------------------------------------------------------- time MLP
__global__ void k_time(const float* __restrict__ emb,
                       const float* __restrict__ Wt1, const float* __restrict__ bt1,
                       const float* __restrict__ Wt2, const float* __restrict__ bt2,
                       const int*   __restrict__ time, int B) {
    __shared__ float z[MAXB*32];
    int t = threadIdx.x;
    int b = t >> 5, c = t & 31;
    const float* e = emb + time[b]*32;
    float v = bt1[c];
    #pragma unroll
    for (int j = 0; j < 32; j++) v += e[j]*Wt1[j*32+c];
    v = v / (1.f + expf(-v));                  // silu
    z[b*32+c] = v;
    __syncthreads();
    float o = bt2[c];
    #pragma unroll
    for (int j = 0; j < 32; j++) o += z[b*32+j]*Wt2[j*32+c];
    dT[b*32+c] = o;
}

// ---------------------------------------------------------------- conv k=5
#define KC0 42
__global__ void k_conv0(const float* __restrict__ x, const int* __restrict__ nb5,
                        const float* __restrict__ W0, int N) {
    __shared__ float sW[KC0*256];              // 42 KiB (front reused for stats)
    int row = blockIdx.x*256 + threadIdx.x;
    float acc[32];
    #pragma unroll
    for (int c = 0; c < 32; c++) acc[c] = 0.f;

    for (int k0 = 0; k0 < 125; k0 += KC0) {
        int kc = min(KC0, 125 - k0);
        int n4 = kc*64;
        const float4* src = (const float4*)(W0 + k0*256);
        for (int i = threadIdx.x; i < n4; i += 256)
            ((float4*)sW)[i] = src[i];
        __syncthreads();
        if (row < N) {
            for (int kk = 0; kk < kc; kk++) {
                int idx = nb5[(size_t)(k0+kk)*N + row];
                if (idx < N) {
                    const float4* xr = (const float4*)(x + (size_t)idx*8);
                    float4 a = xr[0], b = xr[1];
                    float xv[8] = {a.x,a.y,a.z,a.w,b.x,b.y,b.z,b.w};
                    const float* w = sW + kk*256;
                    #pragma unroll
                    for (int j = 0; j < 8; j++)
                        #pragma unroll
                        for (int c = 0; c < 32; c++)
                            acc[c] += xv[j]*w[j*32+c];
                }
            }
        }
        __syncthreads();
    }
    if (row < N) {
        float4* o = (float4*)(dH0 + (size_t)row*32);
        #pragma unroll
        for (int q = 0; q < 8; q++)
            o[q] = make_float4(acc[q*4],acc[q*4+1],acc[q*4+2],acc[q*4+3]);
    }
    block_stats<32>(acc, sW, dPA + blockIdx.x*64);
}

// ------------------------- h = [bnrelu(H0), T[batch]] ; R1=h@Wb1 ; YDS=h@Wds
__global__ void k_blockin(const float* __restrict__ Wb1, const float* __restrict__ Wds,
                          const int* __restrict__ bidx, int N) {
    __shared__ float sW1[64*16];
    __shared__ float sWd[64*64];
    __shared__ float ssc[32], ssh[32];
    __shared__ float sred[8*128];
    for (int i = threadIdx.x; i < 64*16; i += 256) sW1[i] = Wb1[i];
    for (int i = threadIdx.x; i < 64*64; i += 256) sWd[i] = Wds[i];
    if (threadIdx.x < 32) { ssc[threadIdx.x] = dSC[0][threadIdx.x];
                            ssh[threadIdx.x] = dSH[0][threadIdx.x]; }
    __syncthreads();
    int row = blockIdx.x*256 + threadIdx.x;
    bool valid = row < N;

    float r1[16]; float yd[64];
    #pragma unroll
    for (int c = 0; c < 16; c++) r1[c] = 0.f;
    #pragma unroll
    for (int c = 0; c < 64; c++) yd[c] = 0.f;

    if (valid) {
        const float* h0 = dH0 + (size_t)row*32;
        const float* tp = dT  + (size_t)bidx[row]*32;
        #pragma unroll 4
        for (int j = 0; j < 32; j++) {
            float hj = fmaxf(ssc[j]*h0[j] + ssh[j], 0.f);
            #pragma unroll
            for (int c = 0; c < 16; c++) r1[c] += hj*sW1[j*16+c];
            #pragma unroll
            for (int c = 0; c < 64; c++) yd[c] += hj*sWd[j*64+c];
        }
        #pragma unroll 4
        for (int j = 32; j < 64; j++) {
            float hj = tp[j-32];
            #pragma unroll
            for (int c = 0; c < 16; c++) r1[c] += hj*sW1[j*16+c];
            #pragma unroll
            for (int c = 0; c < 64; c++) yd[c] += hj*sWd[j*64+c];
        }
        float4* o1 = (float4*)(dR1 + (size_t)row*16);
        #pragma unroll
        for (int q = 0; q < 4; q++)
            o1[q] = make_float4(r1[q*4],r1[q*4+1],r1[q*4+2],r1[q*4+3]);
        float4* od = (float4*)(dYDS + (size_t)row*64);
        #pragma unroll
        for (int q = 0; q < 16; q++)
            od[q] = make_float4(yd[q*4],yd[q*4+1],yd[q*4+2],yd[q*4+3]);
    }
    block_stats<16>(r1, sred, dPA + blockIdx.x*32);
    block_stats<64>(yd, sred, dPB + blockIdx.x*128);
}

// ---------------------------------------------------------------- conv k=3
__global__ void k_conv3(const int* __restrict__ nb3, const float* __restrict__ Wb2, int N) {
    __shared__ float sW[27*256];               // 27 KiB
    __shared__ float ssc[16], ssh[16];
    __shared__ float sred[8*32];
    for (int i = threadIdx.x; i < 27*256; i += 256) sW[i] = Wb2[i];
    if (threadIdx.x < 16) { ssc[threadIdx.x] = dSC[1][threadIdx.x];
                            ssh[threadIdx.x] = dSH[1][threadIdx.x]; }
    __syncthreads();
    int row = blockIdx.x*256 + threadIdx.x;
    bool valid = row < N;

    float acc[16];
    #pragma unroll
    for (int c = 0; c < 16; c++) acc[c] = 0.f;

    if (valid) {
        for (int k = 0; k < 27; k++) {
            int idx = nb3[(size_t)k*N + row];
            if (idx < N) {
                const float4* rp = (const float4*)(dR1 + (size_t)idx*16);
                float a[16];
                #pragma unroll
                for (int q = 0; q < 4; q++) {
                    float4 v = rp[q];
                    a[q*4] = v.x; a[q*4+1] = v.y; a[q*4+2] = v.z; a[q*4+3] = v.w;
                }
                #pragma unroll
                for (int j = 0; j < 16; j++) a[j] = fmaxf(ssc[j]*a[j] + ssh[j], 0.f);
                const float* w = sW + k*256;
                #pragma unroll
                for (int j = 0; j < 16; j++)
                    #pragma unroll
                    for (int c = 0; c < 16; c++)
                        acc[c] += a[j]*w[j*16+c];
            }
        }
        float4* o = (float4*)(dR2 + (size_t)row*16);
        #pragma unroll
        for (int q = 0; q < 4; q++)
            o[q] = make_float4(acc[q*4],acc[q*4+1],acc[q*4+2],acc[q*4+3]);
    }
    block_stats<16>(acc, sred, dPA + blockIdx.x*32);
}

// ---------------------------------------------------- Y3 = bnrelu(R2) @ Wb3
__global__ void k_y3(const float* __restrict__ Wb3, int N) {
    __shared__ float sW[16*64];
    __shared__ float ssc[16], ssh[16];
    __shared__ float sred[8*128];
    for (int i = threadIdx.x; i < 16*64; i += 256) sW[i] = Wb3[i];
    if (threadIdx.x < 16) { ssc[threadIdx.x] = dSC[2][threadIdx.x];
                            ssh[threadIdx.x] = dSH[2][threadIdx.x]; }
    __syncthreads();
    int row = blockIdx.x*256 + threadIdx.x;
    bool valid = row < N;

    float y[64];
    #pragma unroll
    for (int c = 0; c < 64; c++) y[c] = 0.f;

    if (valid) {
        const float* rp = dR2 + (size_t)row*16;
        float a[16];
        #pragma unroll
        for (int j = 0; j < 16; j++) a[j] = fmaxf(ssc[j]*rp[j] + ssh[j], 0.f);
        #pragma unroll
        for (int j = 0; j < 16; j++)
            #pragma unroll
            for (int c = 0; c < 64; c++)
                y[c] += a[j]*sW[j*64+c];
        float4* o = (float4*)(dY3 + (size_t)row*64);
        #pragma unroll
        for (int q = 0; q < 16; q++)
            o[q] = make_float4(y[q*4],y[q*4+1],y[q*4+2],y[q*4+3]);
    }
    block_stats<64>(y, sred, dPA + blockIdx.x*128);
}

// -------------------------------------- H2 = relu(bn3(Y3) + bnds(YDS))
__global__ void k_h2(int N) {
    int i = blockIdx.x*256 + threadIdx.x;       // float4 index
    int total4 = N*16;
    if (i >= total4) return;
    int c0 = (i*4) & 63;
    float4 y  = ((const float4*)dY3 )[i];
    float4 yd = ((const float4*)dYDS)[i];
    float4 r;
    r.x = fmaxf(dSC[3][c0+0]*y.x + dSH[3][c0+0] + dSC[4][c0+0]*yd.x + dSH[4][c0+0], 0.f);
    r.y = fmaxf(dSC[3][c0+1]*y.y + dSH[3][c0+1] + dSC[4][c0+1]*yd.y + dSH[4][c0+1], 0.f);
    r.z = fmaxf(dSC[3][c0+2]*y.z + dSH[3][c0+2] + dSC[4][c0+2]*yd.z + dSH[4][c0+2], 0.f);
    r.w = fmaxf(dSC[3][c0+3]*y.w + dSH[3][c0+3] + dSC[4][c0+3]*yd.w + dSH[4][c0+3], 0.f);
    ((float4*)dH2)[i] = r;
}

// ---------------------------------------------------------------- conv k=2
#define KC2 2
__global__ void k_conv2(const int* __restrict__ nb2, const float* __restrict__ Wd,
                        int M, int N) {
    __shared__ float sW[KC2*4096];             // 32 KiB
    __shared__ float sred[8*128];
    int row = blockIdx.x*256 + threadIdx.x;
    float acc[64];
    #pragma unroll
    for (int c = 0; c < 64; c++) acc[c] = 0.f;

    for (int k0 = 0; k0 < 8; k0 += KC2) {
        const float4* src = (const float4*)(Wd + k0*4096);
        for (int i = threadIdx.x; i < KC2*1024; i += 256)
            ((float4*)sW)[i] = src[i];
        __syncthreads();
        if (row < M) {
            for (int kk = 0; kk < KC2; kk++) {
                int idx = nb2[(size_t)(k0+kk)*M + row];
                if (idx < N) {
                    const float4* hp = (const float4*)(dH2 + (size_t)idx*64);
                    const float* w = sW + kk*4096;
                    #pragma unroll 2
                    for (int q = 0; q < 16; q++) {
                        float4 h4 = hp[q];
                        const float* wq = w + q*256;
                        #pragma unroll
                        for (int c = 0; c < 64; c++) acc[c] += h4.x*wq[c];
                        #pragma unroll
                        for (int c = 0; c < 64; c++) acc[c] += h4.y*wq[64+c];
                        #pragma unroll
                        for (int c = 0; c < 64; c++) acc[c] += h4.z*wq[128+c];
                        #pragma unroll
                        for (int c = 0; c < 64; c++) acc[c] += h4.w*wq[192+c];
                    }
                }
            }
        }
        __syncthreads();
    }
    if (row < M) {
        float4* o = (float4*)(dORAW + (size_t)row*64);
        #pragma unroll
        for (int q = 0; q < 16; q++)
            o[q] = make_float4(acc[q*4],acc[q*4+1],acc[q*4+2],acc[q*4+3]);
    }
    block_stats<64>(acc, sred, dPA + blockIdx.x*128);
}

// ---------------------------------------------------- out = relu(bn(ORAW))
__global__ void k_apply(float* __restrict__ out, int M) {
    int i = blockIdx.x*256 + threadIdx.x;       // float4 index
    int total4 = M*16;
    if (i >= total4) return;
    int c0 = (i*4) & 63;
    float4 v = ((const float4*)dORAW)[i];
    float4 r;
    r.x = fmaxf(dSC[5][c0+0]*v.x + dSH[5][c0+0], 0.f);
    r.y = fmaxf(dSC[5][c0+1]*v.y + dSH[5][c0+1], 0.f);
    r.z = fmaxf(dSC[5][c0+2]*v.z + dSH[5][c0+2], 0.f);
    r.w = fmaxf(dSC[5][c0+3]*v.w + dSH[5][c0+3], 0.f);
    ((float4*)out)[i] = r;
}

// ---------------------------------------------------------------------------
extern "C" void kernel_launch(void* const* d_in, const int* in_sizes, int n_in,
                              void* d_out, int out_size) {
    const float* x      = (const float*)d_in[0];
    const float* W0     = (const float*)d_in[1];
    const float* g0     = (const float*)d_in[2];
    const float* b0     = (const float*)d_in[3];
    const float* emb    = (const float*)d_in[4];
    const float* Wt1    = (const float*)d_in[5];
    const float* bt1    = (const float*)d_in[6];
    const float* Wt2    = (const float*)d_in[7];
    const float* bt2    = (const float*)d_in[8];
    const float* Wb1    = (const float*)d_in[9];
    const float* gb1    = (const float*)d_in[10];
    const float* bb1    = (const float*)d_in[11];
    const float* Wb2    = (const float*)d_in[12];
    const float* gb2    = (const float*)d_in[13];
    const float* bb2    = (const float*)d_in[14];
    const float* Wb3    = (const float*)d_in[15];
    const float* gb3    = (const float*)d_in[16];
    const float* bb3    = (const float*)d_in[17];
    const float* Wds    = (const float*)d_in[18];
    const float* gds    = (const float*)d_in[19];
    const float* bds    = (const float*)d_in[20];
    const float* Wd     = (const float*)d_in[21];
    const float* gd     = (const float*)d_in[22];
    const float* bd     = (const float*)d_in[23];
    const int*   time   = (const int*)  d_in[24];
    const int*   bidx   = (const int*)  d_in[25];
    const int*   nb5    = (const int*)  d_in[26];
    const int*   nb3    = (const int*)  d_in[27];
    const int*   nb2    = (const int*)  d_in[28];
    float* out = (float*)d_out;

    int N = in_sizes[0] / 8;
    int B = in_sizes[24];
    int M = in_sizes[28] / 8;

    int nb = (N + 255) / 256;
    int mb = (M + 255) / 256;

    // device pointers to __device__ globals for k_fin
    float* pA; cudaGetSymbolAddress((void**)&pA, dPA);
    float* pB; cudaGetSymbolAddress((void**)&pB, dPB);

    k_time<<<1, B*32>>>(emb, Wt1, bt1, Wt2, bt2, time, B);
    k_conv0<<<nb, 256>>>(x, nb5, W0, N);
    k_fin<<<1, 1024>>>(pA, nb, 32, N, g0, b0, 0);
    k_blockin<<<nb, 256>>>(Wb1, Wds, bidx, N);
    k_fin2<<<2, 1024>>>(nb, N, gb1, bb1, gds, bds);
    k_conv3<<<nb, 256>>>(nb3, Wb2, N);
    k_fin<<<1, 1024>>>(pA, nb, 16, N, gb2, bb2, 2);
    k_y3<<<nb, 256>>>(Wb3, N);
    k_fin<<<1, 1024>>>(pA, nb, 64, N, gb3, bb3, 3);
    k_h2<<<(N*16 + 255)/256, 256>>>(N);
    k_conv2<<<mb, 256>>>(nb2, Wd, M, N);
    k_fin<<<1, 1024>>>(pA, mb, 64, M, gd, bd, 5);
    k_apply<<<(M*16 + 255)/256, 256>>>(out, M);
}

// round 3
// speedup vs baseline: 1.0392x; 1.0392x over previous
#include <cuda_runtime.h>
#include <math.h>

// ---------------------------------------------------------------------------
// MinkUNet block, round 3: lean producers (no fused stats), float4 LDS
// weights, split blockin, vectorized stats + parallel finalize.
// ---------------------------------------------------------------------------

#define MAXN 131072
#define MAXM 131072
#define MAXB 64
#define SB   256     // stats partial blocks (fixed -> deterministic)

__device__ __align__(16) float dH0 [MAXN*32];   // conv0 raw
__device__ __align__(16) float dR1 [MAXN*16];   // h@Wb1 raw
__device__ __align__(16) float dR2 [MAXN*16];   // conv3 raw
__device__ __align__(16) float dY3 [MAXN*64];   // r@Wb3 raw
__device__ __align__(16) float dYDS[MAXN*64];   // h@Wds raw
__device__ __align__(16) float dH2 [MAXN*64];   // residual out
__device__ __align__(16) float dORAW[MAXM*64];  // conv2 raw
__device__ __align__(16) float dT  [MAXB*32];   // time mlp out
__device__ float dPA[SB*128];                   // partials [block][2C]
__device__ float dPB[SB*128];
__device__ float dSC[6][64];                    // per-BN scale
__device__ float dSH[6][64];                    // per-BN shift

// ---------------------------------------------------------------- time MLP
__global__ void k_time(const float* __restrict__ emb,
                       const float* __restrict__ Wt1, const float* __restrict__ bt1,
                       const float* __restrict__ Wt2, const float* __restrict__ bt2,
                       const int*   __restrict__ time, int B) {
    __shared__ float z[MAXB*32];
    int t = threadIdx.x;
    int b = t >> 5, c = t & 31;
    const float* e = emb + time[b]*32;
    float v = bt1[c];
    #pragma unroll
    for (int j = 0; j < 32; j++) v += e[j]*Wt1[j*32+c];
    v = v / (1.f + expf(-v));                  // silu
    z[b*32+c] = v;
    __syncthreads();
    float o = bt2[c];
    #pragma unroll
    for (int j = 0; j < 32; j++) o += z[b*32+j]*Wt2[j*32+c];
    dT[b*32+c] = o;
}

// ---------------------------------------------------------------- stats
// Vectorized deterministic per-channel sum/sumsq. stride SB*256*4 % C == 0
// so each (thread,slot) owns a fixed channel.
__global__ void k_stats(const float4* __restrict__ src, int n4, int C,
                        float* __restrict__ part) {
    int t = threadIdx.x;
    int gid = blockIdx.x*256 + t;
    float s0=0,s1=0,s2=0,s3=0,q0=0,q1=0,q2=0,q3=0;
    for (int i = gid; i < n4; i += SB*256) {
        float4 v = src[i];
        s0+=v.x; q0+=v.x*v.x; s1+=v.y; q1+=v.y*v.y;
        s2+=v.z; q2+=v.z*v.z; s3+=v.w; q3+=v.w*v.w;
    }
    __shared__ float sh[256*8];
    sh[t*8+0]=s0; sh[t*8+1]=s1; sh[t*8+2]=s2; sh[t*8+3]=s3;
    sh[t*8+4]=q0; sh[t*8+5]=q1; sh[t*8+6]=q2; sh[t*8+7]=q3;
    __syncthreads();
    if (t < C) {              // channel of (tt,j) is (4*tt+j)%C
        int j = t & 3, t0 = t >> 2, step = C >> 2;
        float S = 0.f, Q = 0.f;
        for (int tt = t0; tt < 256; tt += step) { S += sh[tt*8+j]; Q += sh[tt*8+4+j]; }
        part[blockIdx.x*2*C + t]     = S;
        part[blockIdx.x*2*C + C + t] = Q;
    }
}

// ---------------------------------------------------------------- finalize
__global__ void k_fin(const float* __restrict__ part, int nblocks, int C, int rows,
                      const float* __restrict__ g, const float* __restrict__ b,
                      int slot) {
    __shared__ float red[8*128];
    int t = threadIdx.x, C2 = 2*C;
    if (t < C2*8) {
        int sub = t / C2, e = t - sub*C2;
        float s = 0.f;
        for (int i = sub; i < nblocks; i += 8) s += part[i*C2 + e];
        red[sub*C2 + e] = s;
    }
    __syncthreads();
    if (t < C) {
        float S = 0.f, SS = 0.f;
        #pragma unroll
        for (int k = 0; k < 8; k++) { S += red[k*C2 + t]; SS += red[k*C2 + C + t]; }
        float inv  = 1.f / (float)rows;
        float mean = S * inv;
        float var  = SS * inv - mean*mean;
        float sc   = g[t] * rsqrtf(var + 1e-5f);
        dSC[slot][t] = sc;
        dSH[slot][t] = b[t] - mean*sc;
    }
}

// ---------------------------------------------------------------- conv k=5
#define KC0 42
__global__ void __launch_bounds__(256) k_conv0(const float* __restrict__ x,
                        const int* __restrict__ nb5,
                        const float* __restrict__ W0, int N) {
    __shared__ float4 sW[KC0*64];              // 42 KiB
    int row = blockIdx.x*256 + threadIdx.x;
    float4 acc[8];
    #pragma unroll
    for (int c = 0; c < 8; c++) acc[c] = make_float4(0.f,0.f,0.f,0.f);

    for (int k0 = 0; k0 < 125; k0 += KC0) {
        int kc = min(KC0, 125 - k0);
        const float4* src = (const float4*)(W0 + k0*256);
        for (int i = threadIdx.x; i < kc*64; i += 256) sW[i] = src[i];
        __syncthreads();
        if (row < N) {
            for (int kk = 0; kk < kc; kk++) {
                int idx = nb5[(size_t)(k0+kk)*N + row];
                if (idx < N) {
                    const float4* xr = (const float4*)(x + (size_t)idx*8);
                    float4 a = xr[0], b = xr[1];
                    float xv[8] = {a.x,a.y,a.z,a.w,b.x,b.y,b.z,b.w};
                    const float4* wk = sW + kk*64;
                    #pragma unroll
                    for (int j = 0; j < 8; j++) {
                        #pragma unroll
                        for (int c4 = 0; c4 < 8; c4++) {
                            float4 w = wk[j*8 + c4];
                            acc[c4].x += xv[j]*w.x; acc[c4].y += xv[j]*w.y;
                            acc[c4].z += xv[j]*w.z; acc[c4].w += xv[j]*w.w;
                        }
                    }
                }
            }
        }
        __syncthreads();
    }
    if (row < N) {
        float4* o = (float4*)(dH0 + (size_t)row*32);
        #pragma unroll
        for (int q = 0; q < 8; q++) o[q] = acc[q];
    }
}

// ---------------------------------------------- R1 = [bnrelu(H0),T] @ Wb1
__global__ void __launch_bounds__(256) k_r1(const float* __restrict__ Wb1,
                     const int* __restrict__ bidx, int N) {
    __shared__ float4 sW[64*4];                // 64x16
    __shared__ float ssc[32], ssh[32];
    if (threadIdx.x < 256) { int i = threadIdx.x; if (i < 256) sW[i] = ((const float4*)Wb1)[i]; }
    if (threadIdx.x < 32) { ssc[threadIdx.x] = dSC[0][threadIdx.x];
                            ssh[threadIdx.x] = dSH[0][threadIdx.x]; }
    __syncthreads();
    int row = blockIdx.x*256 + threadIdx.x;
    if (row >= N) return;

    float4 acc[4];
    #pragma unroll
    for (int c = 0; c < 4; c++) acc[c] = make_float4(0.f,0.f,0.f,0.f);

    const float4* h4 = (const float4*)(dH0 + (size_t)row*32);
    #pragma unroll
    for (int q = 0; q < 8; q++) {
        float4 v = h4[q];
        float hv[4] = {v.x,v.y,v.z,v.w};
        #pragma unroll
        for (int u = 0; u < 4; u++) {
            int j = q*4+u;
            float hj = fmaxf(ssc[j]*hv[u] + ssh[j], 0.f);
            #pragma unroll
            for (int c4 = 0; c4 < 4; c4++) {
                float4 w = sW[j*4+c4];
                acc[c4].x += hj*w.x; acc[c4].y += hj*w.y;
                acc[c4].z += hj*w.z; acc[c4].w += hj*w.w;
            }
        }
    }
    const float4* t4 = (const float4*)(dT + (size_t)bidx[row]*32);
    #pragma unroll
    for (int q = 0; q < 8; q++) {
        float4 v = t4[q];
        float hv[4] = {v.x,v.y,v.z,v.w};
        #pragma unroll
        for (int u = 0; u < 4; u++) {
            int j = 32 + q*4+u;
            float hj = hv[u];
            #pragma unroll
            for (int c4 = 0; c4 < 4; c4++) {
                float4 w = sW[j*4+c4];
                acc[c4].x += hj*w.x; acc[c4].y += hj*w.y;
                acc[c4].z += hj*w.z; acc[c4].w += hj*w.w;
            }
        }
    }
    float4* o = (float4*)(dR1 + (size_t)row*16);
    #pragma unroll
    for (int q = 0; q < 4; q++) o[q] = acc[q];
}

// ---------------------------------------------- YDS = [bnrelu(H0),T] @ Wds
__global__ void __launch_bounds__(256,2) k_yds(const float* __restrict__ Wds,
                      const int* __restrict__ bidx, int N) {
    __shared__ float4 sW[64*16];               // 64x64 = 16 KiB
    __shared__ float ssc[32], ssh[32];
    for (int i = threadIdx.x; i < 64*16; i += 256) sW[i] = ((const float4*)Wds)[i];
    if (threadIdx.x < 32) { ssc[threadIdx.x] = dSC[0][threadIdx.x];
                            ssh[threadIdx.x] = dSH[0][threadIdx.x]; }
    __syncthreads();
    int row = blockIdx.x*256 + threadIdx.x;
    if (row >= N) return;

    float4 acc[16];
    #pragma unroll
    for (int c = 0; c < 16; c++) acc[c] = make_float4(0.f,0.f,0.f,0.f);

    const float4* h4 = (const float4*)(dH0 + (size_t)row*32);
    #pragma unroll
    for (int q = 0; q < 8; q++) {
        float4 v = h4[q];
        float hv[4] = {v.x,v.y,v.z,v.w};
        #pragma unroll
        for (int u = 0; u < 4; u++) {
            int j = q*4+u;
            float hj = fmaxf(ssc[j]*hv[u] + ssh[j], 0.f);
            #pragma unroll
            for (int c4 = 0; c4 < 16; c4++) {
                float4 w = sW[j*16+c4];
                acc[c4].x += hj*w.x; acc[c4].y += hj*w.y;
                acc[c4].z += hj*w.z; acc[c4].w += hj*w.w;
            }
        }
    }
    const float4* t4 = (const float4*)(dT + (size_t)bidx[row]*32);
    #pragma unroll
    for (int q = 0; q < 8; q++) {
        float4 v = t4[q];
        float hv[4] = {v.x,v.y,v.z,v.w};
        #pragma unroll
        for (int u = 0; u < 4; u++) {
            int j = 32 + q*4+u;
            float hj = hv[u];
            #pragma unroll
            for (int c4 = 0; c4 < 16; c4++) {
                float4 w = sW[j*16+c4];
                acc[c4].x += hj*w.x; acc[c4].y += hj*w.y;
                acc[c4].z += hj*w.z; acc[c4].w += hj*w.w;
            }
        }
    }
    float4* o = (float4*)(dYDS + (size_t)row*64);
    #pragma unroll
    for (int q = 0; q < 16; q++) o[q] = acc[q];
}

// ---------------------------------------------------------------- conv k=3
__global__ void __launch_bounds__(256) k_conv3(const int* __restrict__ nb3,
                        const float* __restrict__ Wb2, int N) {
    __shared__ float4 sW[27*64];               // 27 KiB
    __shared__ float ssc[16], ssh[16];
    for (int i = threadIdx.x; i < 27*64; i += 256) sW[i] = ((const float4*)Wb2)[i];
    if (threadIdx.x < 16) { ssc[threadIdx.x] = dSC[1][threadIdx.x];
                            ssh[threadIdx.x] = dSH[1][threadIdx.x]; }
    __syncthreads();
    int row = blockIdx.x*256 + threadIdx.x;
    if (row >= N) return;

    float4 acc[4];
    #pragma unroll
    for (int c = 0; c < 4; c++) acc[c] = make_float4(0.f,0.f,0.f,0.f);

    for (int k = 0; k < 27; k++) {
        int idx = nb3[(size_t)k*N + row];
        if (idx < N) {
            const float4* rp = (const float4*)(dR1 + (size_t)idx*16);
            const float4* wk = sW + k*64;
            #pragma unroll
            for (int q = 0; q < 4; q++) {
                float4 v = rp[q];
                float av[4] = {v.x,v.y,v.z,v.w};
                #pragma unroll
                for (int u = 0; u < 4; u++) {
                    int j = q*4+u;
                    float aj = fmaxf(ssc[j]*av[u] + ssh[j], 0.f);
                    #pragma unroll
                    for (int c4 = 0; c4 < 4; c4++) {
                        float4 w = wk[j*4+c4];
                        acc[c4].x += aj*w.x; acc[c4].y += aj*w.y;
                        acc[c4].z += aj*w.z; acc[c4].w += aj*w.w;
                    }
                }
            }
        }
    }
    float4* o = (float4*)(dR2 + (size_t)row*16);
    #pragma unroll
    for (int q = 0; q < 4; q++) o[q] = acc[q];
}

// ---------------------------------------------------- Y3 = bnrelu(R2) @ Wb3
__global__ void __launch_bounds__(256,2) k_y3(const float* __restrict__ Wb3, int N) {
    __shared__ float4 sW[16*16];               // 16x64
    __shared__ float ssc[16], ssh[16];
    if (threadIdx.x < 256) sW[threadIdx.x] = ((const float4*)Wb3)[threadIdx.x];
    if (threadIdx.x < 16) { ssc[threadIdx.x] = dSC[2][threadIdx.x];
                            ssh[threadIdx.x] = dSH[2][threadIdx.x]; }
    __syncthreads();
    int row = blockIdx.x*256 + threadIdx.x;
    if (row >= N) return;

    float4 acc[16];
    #pragma unroll
    for (int c = 0; c < 16; c++) acc[c] = make_float4(0.f,0.f,0.f,0.f);

    const float4* rp = (const float4*)(dR2 + (size_t)row*16);
    #pragma unroll
    for (int q = 0; q < 4; q++) {
        float4 v = rp[q];
        float av[4] = {v.x,v.y,v.z,v.w};
        #pragma unroll
        for (int u = 0; u < 4; u++) {
            int j = q*4+u;
            float aj = fmaxf(ssc[j]*av[u] + ssh[j], 0.f);
            #pragma unroll
            for (int c4 = 0; c4 < 16; c4++) {
                float4 w = sW[j*16+c4];
                acc[c4].x += aj*w.x; acc[c4].y += aj*w.y;
                acc[c4].z += aj*w.z; acc[c4].w += aj*w.w;
            }
        }
    }
    float4* o = (float4*)(dY3 + (size_t)row*64);
    #pragma unroll
    for (int q = 0; q < 16; q++) o[q] = acc[q];
}

// -------------------------------------- H2 = relu(bn3(Y3) + bnds(YDS))
__global__ void k_h2(int N) {
    int i = blockIdx.x*256 + threadIdx.x;
    int total4 = N*16;
    if (i >= total4) return;
    int c0 = (i*4) & 63;
    float4 y  = ((const float4*)dY3 )[i];
    float4 yd = ((const float4*)dYDS)[i];
    float4 r;
    r.x = fmaxf(dSC[3][c0+0]*y.x + dSH[3][c0+0] + dSC[4][c0+0]*yd.x + dSH[4][c0+0], 0.f);
    r.y = fmaxf(dSC[3][c0+1]*y.y + dSH[3][c0+1] + dSC[4][c0+1]*yd.y + dSH[4][c0+1], 0.f);
    r.z = fmaxf(dSC[3][c0+2]*y.z + dSH[3][c0+2] + dSC[4][c0+2]*yd.z + dSH[4][c0+2], 0.f);
    r.w = fmaxf(dSC[3][c0+3]*y.w + dSH[3][c0+3] + dSC[4][c0+3]*yd.w + dSH[4][c0+3], 0.f);
    ((float4*)dH2)[i] = r;
}

// ---------------------------------------------------------------- conv k=2
#define KC2 2
__global__ void __launch_bounds__(256,2) k_conv2(const int* __restrict__ nb2,
                        const float* __restrict__ Wd, int M, int N) {
    __shared__ float4 sW[KC2*1024];            // 32 KiB
    int row = blockIdx.x*256 + threadIdx.x;
    float4 acc[16];
    #pragma unroll
    for (int c = 0; c < 16; c++) acc[c] = make_float4(0.f,0.f,0.f,0.f);

    for (int k0 = 0; k0 < 8; k0 += KC2) {
        const float4* src = (const float4*)(Wd + k0*4096);
        for (int i = threadIdx.x; i < KC2*1024; i += 256) sW[i] = src[i];
        __syncthreads();
        if (row < M) {
            #pragma unroll
            for (int kk = 0; kk < KC2; kk++) {
                int idx = nb2[(size_t)(k0+kk)*M + row];
                if (idx < N) {
                    const float4* hp = (const float4*)(dH2 + (size_t)idx*64);
                    const float4* wk = sW + kk*1024;
                    #pragma unroll
                    for (int q = 0; q < 16; q++) {
                        float4 h4 = hp[q];
                        float hv[4] = {h4.x,h4.y,h4.z,h4.w};
                        #pragma unroll
                        for (int u = 0; u < 4; u++) {
                            int j = q*4+u;
                            const float4* wj = wk + j*16;
                            float hj = hv[u];
                            #pragma unroll
                            for (int c4 = 0; c4 < 16; c4++) {
                                float4 w = wj[c4];
                                acc[c4].x += hj*w.x; acc[c4].y += hj*w.y;
                                acc[c4].z += hj*w.z; acc[c4].w += hj*w.w;
                            }
                        }
                    }
                }
            }
        }
        __syncthreads();
    }
    if (row < M) {
        float4* o = (float4*)(dORAW + (size_t)row*64);
        #pragma unroll
        for (int q = 0; q < 16; q++) o[q] = acc[q];
    }
}

// ---------------------------------------------------- out = relu(bn(ORAW))
__global__ void k_apply(float* __restrict__ out, int M) {
    int i = blockIdx.x*256 + threadIdx.x;
    int total4 = M*16;
    if (i >= total4) return;
    int c0 = (i*4) & 63;
    float4 v = ((const float4*)dORAW)[i];
    float4 r;
    r.x = fmaxf(dSC[5][c0+0]*v.x + dSH[5][c0+0], 0.f);
    r.y = fmaxf(dSC[5][c0+1]*v.y + dSH[5][c0+1], 0.f);
    r.z = fmaxf(dSC[5][c0+2]*v.z + dSH[5][c0+2], 0.f);
    r.w = fmaxf(dSC[5][c0+3]*v.w + dSH[5][c0+3], 0.f);
    ((float4*)out)[i] = r;
}

// ---------------------------------------------------------------------------
extern "C" void kernel_launch(void* const* d_in, const int* in_sizes, int n_in,
                              void* d_out, int out_size) {
    const float* x      = (const float*)d_in[0];
    const float* W0     = (const float*)d_in[1];
    const float* g0     = (const float*)d_in[2];
    const float* b0     = (const float*)d_in[3];
    const float* emb    = (const float*)d_in[4];
    const float* Wt1    = (const float*)d_in[5];
    const float* bt1    = (const float*)d_in[6];
    const float* Wt2    = (const float*)d_in[7];
    const float* bt2    = (const float*)d_in[8];
    const float* Wb1    = (const float*)d_in[9];
    const float* gb1    = (const float*)d_in[10];
    const float* bb1    = (const float*)d_in[11];
    const float* Wb2    = (const float*)d_in[12];
    const float* gb2    = (const float*)d_in[13];
    const float* bb2    = (const float*)d_in[14];
    const float* Wb3    = (const float*)d_in[15];
    const float* gb3    = (const float*)d_in[16];
    const float* bb3    = (const float*)d_in[17];
    const float* Wds    = (const float*)d_in[18];
    const float* gds    = (const float*)d_in[19];
    const float* bds    = (const float*)d_in[20];
    const float* Wd     = (const float*)d_in[21];
    const float* gd     = (const float*)d_in[22];
    const float* bd     = (const float*)d_in[23];
    const int*   time   = (const int*)  d_in[24];
    const int*   bidx   = (const int*)  d_in[25];
    const int*   nb5    = (const int*)  d_in[26];
    const int*   nb3    = (const int*)  d_in[27];
    const int*   nb2    = (const int*)  d_in[28];
    float* out = (float*)d_out;

    int N = in_sizes[0] / 8;
    int B = in_sizes[24];
    int M = in_sizes[28] / 8;

    int nb = (N + 255) / 256;
    int mb = (M + 255) / 256;

    float4 *pH0, *pR1, *pR2, *pY3, *pYDS, *pOR;
    float *pA, *pB;
    cudaGetSymbolAddress((void**)&pH0, dH0);
    cudaGetSymbolAddress((void**)&pR1, dR1);
    cudaGetSymbolAddress((void**)&pR2, dR2);
    cudaGetSymbolAddress((void**)&pY3, dY3);
    cudaGetSymbolAddress((void**)&pYDS, dYDS);
    cudaGetSymbolAddress((void**)&pOR, dORAW);
    cudaGetSymbolAddress((void**)&pA, dPA);
    cudaGetSymbolAddress((void**)&pB, dPB);

    k_time<<<1, B*32>>>(emb, Wt1, bt1, Wt2, bt2, time, B);

    k_conv0<<<nb, 256>>>(x, nb5, W0, N);
    k_stats<<<SB, 256>>>(pH0, N*8, 32, pA);
    k_fin<<<1, 1024>>>(pA, SB, 32, N, g0, b0, 0);

    k_r1 <<<nb, 256>>>(Wb1, bidx, N);
    k_yds<<<nb, 256>>>(Wds, bidx, N);
    k_stats<<<SB, 256>>>(pR1, N*4, 16, pA);
    k_stats<<<SB, 256>>>(pYDS, N*16, 64, pB);
    k_fin<<<1, 1024>>>(pA, SB, 16, N, gb1, bb1, 1);
    k_fin<<<1, 1024>>>(pB, SB, 64, N, gds, bds, 4);

    k_conv3<<<nb, 256>>>(nb3, Wb2, N);
    k_stats<<<SB, 256>>>(pR2, N*4, 16, pA);
    k_fin<<<1, 1024>>>(pA, SB, 16, N, gb2, bb2, 2);

    k_y3<<<nb, 256>>>(Wb3, N);
    k_stats<<<SB, 256>>>(pY3, N*16, 64, pA);
    k_fin<<<1, 1024>>>(pA, SB, 64, N, gb3, bb3, 3);

    k_h2<<<(N*16 + 255)/256, 256>>>(N);

    k_conv2<<<mb, 256>>>(nb2, Wd, M, N);
    k_stats<<<SB, 256>>>(pOR, M*16, 64, pA);
    k_fin<<<1, 1024>>>(pA, SB, 64, M, gd, bd, 5);

    k_apply<<<(M*16 + 255)/256, 256>>>(out, M);
}